// round 10
// baseline (speedup 1.0000x reference)
#include <cuda_runtime.h>
#include <math_constants.h>

#define FH 64
#define FW 64
#define FC 128
#define NB 2
#define NROI 256
#define OH 7
#define OW 7
#define NBIN (OH * OW)          // 49
#define SCALE 0.0625f
#define C4 (FC / 4)             // 32 float4 per pixel
#define LVL (NB * FH * FW * FC) // floats per pyramid level (4 MB)

// x-max pyramid, NHWC per level: level k = max over columns [x, x+2^k), k=0..3
__device__ float g_pyr[4][LVL];

// ---------------------------------------------------------------------------
// Kernel 1: NCHW -> NHWC transpose + x-max pyramid build.
// One block per (b, y, channel-quarter): 512 blocks, 32ch x 64px tiles.
// ---------------------------------------------------------------------------
__global__ __launch_bounds__(256) void transpose_build(const float* __restrict__ feat) {
    __shared__ float sA[32][FW + 1];         // 8.3 KB
    __shared__ float sB[32][FW + 1];         // 8.3 KB
    int blk = blockIdx.x;                    // 0..511
    int choff = (blk & 3) * 32;              // channel quarter
    int row = blk >> 2;                      // b*64 + y
    int b = row >> 6;
    int y = row & 63;
    int tid = threadIdx.x;

    // Phase 1: coalesced float4 loads of 32 channels x 64 px (512 float4)
    const float4* src4 = reinterpret_cast<const float4*>(
        feat + (((size_t)b * FC + choff) * FH + y) * FW);
    const size_t cstr4 = (size_t)FH * FW / 4;
    #pragma unroll
    for (int it = 0; it < 2; ++it) {
        int idx = tid + it * 256;            // 0..511
        int c  = idx >> 4;                   // 0..31
        int x4 = idx & 15;
        float4 v = src4[(size_t)c * cstr4 + x4];
        sA[c][x4 * 4 + 0] = v.x;
        sA[c][x4 * 4 + 1] = v.y;
        sA[c][x4 * 4 + 2] = v.z;
        sA[c][x4 * 4 + 3] = v.w;
    }
    __syncthreads();

    size_t dbase = (size_t)row * FW * FC + choff;

#define STORE_LEVEL(buf, k)                                                 \
    {                                                                       \
        float* dst = g_pyr[k] + dbase;                                      \
        _Pragma("unroll")                                                   \
        for (int it = 0; it < 2; ++it) {                                    \
            int idx = tid + it * 256;        /* 0..511 */                   \
            int c4 = idx & 7;                /* 8 float4 chunks of 32 ch */ \
            int x  = idx >> 3;               /* 0..63 */                    \
            float4 v;                                                       \
            v.x = buf[c4 * 4 + 0][x];                                       \
            v.y = buf[c4 * 4 + 1][x];                                       \
            v.z = buf[c4 * 4 + 2][x];                                       \
            v.w = buf[c4 * 4 + 3][x];                                       \
            reinterpret_cast<float4*>(dst + (size_t)x * FC)[c4] = v;        \
        }                                                                   \
    }

#define BUILD_LEVEL(dstbuf, srcbuf, step)                                   \
    {                                                                       \
        _Pragma("unroll")                                                   \
        for (int it = 0; it < 8; ++it) {                                    \
            int idx = tid + it * 256;        /* 0..2047 */                  \
            int c = idx >> 6;                                               \
            int x = idx & 63;                                               \
            int x2 = min(x + (step), 63);                                   \
            dstbuf[c][x] = fmaxf(srcbuf[c][x], srcbuf[c][x2]);              \
        }                                                                   \
    }

    STORE_LEVEL(sA, 0)
    BUILD_LEVEL(sB, sA, 1)
    __syncthreads();
    STORE_LEVEL(sB, 1)
    BUILD_LEVEL(sA, sB, 2)
    __syncthreads();
    STORE_LEVEL(sA, 2)
    BUILD_LEVEL(sB, sA, 4)
    __syncthreads();
    STORE_LEVEL(sB, 3)
#undef STORE_LEVEL
#undef BUILD_LEVEL
}

// ---------------------------------------------------------------------------
// Kernel 2: one block (448 thr = 14 warps) per (roi, ph) stripe: 1792 blocks.
// Warp pair (2*pw, 2*pw+1) = bin column pw, rows split even/odd.
// Bin row-segment = 2 pyramid lookups (sparse-table RMQ); per warp
// <=5 rows x 2 independent LDG.128. Parity halves merged in epilogue.
// ---------------------------------------------------------------------------
__global__ __launch_bounds__(448, 4) void roipool_kernel(const float* __restrict__ rois,
                                                         float* __restrict__ out) {
    __shared__ float4 s_acc[14][C4];         // 7 KB
    __shared__ int s_q[OW][3];               // k, xs0, xs1 per pw
    __shared__ int s_geo[4];                 // b, hs, he, empty

    int bx = blockIdx.x;
    int r  = bx / OH;
    int ph = bx - r * OH;
    int tid  = threadIdx.x;
    int wid  = tid >> 5;
    int lane = tid & 31;

    if (tid < OW) {
        int x1 = (int)(rois[r * 5 + 1] * SCALE);
        int x2 = (int)(rois[r * 5 + 3] * SCALE);
        int w = x2 - x1;
        int ws = x1 + (tid * w) / OW;
        int we = x1 + ((tid + 1) * w + OW - 1) / OW;
        int wp = we - ws;
        int k  = (wp > 0) ? (31 - __clz(wp)) : 0;   // wp <= 10 -> k <= 3
        s_q[tid][0] = k;
        s_q[tid][1] = ws;
        s_q[tid][2] = (wp > 0) ? (we - (1 << k)) : ws;
    } else if (tid < 8) {                    // tid == 7
        int b  = (int)rois[r * 5 + 0];
        int x1 = (int)(rois[r * 5 + 1] * SCALE);
        int y1 = (int)(rois[r * 5 + 2] * SCALE);
        int x2 = (int)(rois[r * 5 + 3] * SCALE);
        int y2 = (int)(rois[r * 5 + 4] * SCALE);
        int h = y2 - y1;
        int w = x2 - x1;
        s_geo[0] = b;
        s_geo[1] = y1 + (ph * h) / OH;
        s_geo[2] = y1 + ((ph + 1) * h + OH - 1) / OH;
        s_geo[3] = (h <= 0 || w <= 0);
    }
    __syncthreads();

    int b  = s_geo[0];
    int hs = s_geo[1];
    int he = s_geo[2];
    int empty = s_geo[3];

    {
        int pw  = wid >> 1;
        int par = wid & 1;
        int k   = s_q[pw][0];
        int xs0 = s_q[pw][1];
        int xs1 = s_q[pw][2];

        float4 acc = make_float4(-CUDART_INF_F, -CUDART_INF_F,
                                 -CUDART_INF_F, -CUDART_INF_F);

        const float4* base = reinterpret_cast<const float4*>(g_pyr[k])
                           + ((size_t)b * FH * FW) * C4 + lane;
        const float4* p0 = base + (size_t)xs0 * C4;
        const float4* p1 = base + (size_t)xs1 * C4;

        #pragma unroll 2
        for (int y = hs + par; y < he; y += 2) {
            size_t ro = (size_t)(y * FW) * C4;
            float4 v0 = p0[ro];
            float4 v1 = p1[ro];
            acc.x = fmaxf(acc.x, fmaxf(v0.x, v1.x));
            acc.y = fmaxf(acc.y, fmaxf(v0.y, v1.y));
            acc.z = fmaxf(acc.z, fmaxf(v0.z, v1.z));
            acc.w = fmaxf(acc.w, fmaxf(v0.w, v1.w));
        }
        s_acc[wid][lane] = acc;              // STS.128, no conflicts
    }
    __syncthreads();

    // Epilogue: 896 outputs for this (r, ph) slice: out[r][c][ph][pw]
    const float* sf = reinterpret_cast<const float*>(s_acc);  // [14][128]
    float* obase = out + (size_t)r * FC * NBIN + ph * OW;
    #pragma unroll
    for (int it = 0; it < 2; ++it) {
        int t = tid + it * 448;
        int c  = t / OW;
        int pw = t - c * OW;
        float v = fmaxf(sf[(2 * pw) * FC + c], sf[(2 * pw + 1) * FC + c]);
        obase[c * NBIN + pw] = empty ? 0.f : v;
    }
}

extern "C" void kernel_launch(void* const* d_in, const int* in_sizes, int n_in,
                              void* d_out, int out_size) {
    const float* feat = (const float*)d_in[0];   // (2,128,64,64) fp32
    const float* rois = (const float*)d_in[1];   // (256,5) fp32
    float* out = (float*)d_out;                  // (256,128,7,7) fp32

    transpose_build<<<NB * FH * 4, 256>>>(feat);
    roipool_kernel<<<NROI * OH, 448>>>(rois, out);
}

// round 11
// speedup vs baseline: 1.1054x; 1.1054x over previous
#include <cuda_runtime.h>
#include <math_constants.h>

#define FH 64
#define FW 64
#define FC 128
#define NB 2
#define NROI 256
#define OH 7
#define OW 7
#define NBIN (OH * OW)          // 49
#define SCALE 0.0625f
#define C4 (FC / 4)             // 32 float4 per pixel
#define LVL (NB * FH * FW * FC) // floats per pyramid level (4 MB)
#define MAXROWS 10              // ceil(63/7)+1

// x-max pyramid, NHWC per level: level k = max over columns [x, x+2^k), k=0..3
__device__ float g_pyr[4][LVL];

// ---------------------------------------------------------------------------
// Kernel 1: NCHW -> NHWC transpose + x-max pyramid build.
// One block per (b, y, channel-quarter): 512 blocks, 32ch x 64px tiles.
// ---------------------------------------------------------------------------
__global__ __launch_bounds__(256) void transpose_build(const float* __restrict__ feat) {
    __shared__ float sA[32][FW + 1];         // 8.3 KB
    __shared__ float sB[32][FW + 1];         // 8.3 KB
    int blk = blockIdx.x;                    // 0..511
    int choff = (blk & 3) * 32;              // channel quarter
    int row = blk >> 2;                      // b*64 + y
    int b = row >> 6;
    int y = row & 63;
    int tid = threadIdx.x;

    const float4* src4 = reinterpret_cast<const float4*>(
        feat + (((size_t)b * FC + choff) * FH + y) * FW);
    const size_t cstr4 = (size_t)FH * FW / 4;
    #pragma unroll
    for (int it = 0; it < 2; ++it) {
        int idx = tid + it * 256;            // 0..511
        int c  = idx >> 4;
        int x4 = idx & 15;
        float4 v = src4[(size_t)c * cstr4 + x4];
        sA[c][x4 * 4 + 0] = v.x;
        sA[c][x4 * 4 + 1] = v.y;
        sA[c][x4 * 4 + 2] = v.z;
        sA[c][x4 * 4 + 3] = v.w;
    }
    __syncthreads();

    size_t dbase = (size_t)row * FW * FC + choff;

#define STORE_LEVEL(buf, k)                                                 \
    {                                                                       \
        float* dst = g_pyr[k] + dbase;                                      \
        _Pragma("unroll")                                                   \
        for (int it = 0; it < 2; ++it) {                                    \
            int idx = tid + it * 256;                                       \
            int c4 = idx & 7;                                               \
            int x  = idx >> 3;                                              \
            float4 v;                                                       \
            v.x = buf[c4 * 4 + 0][x];                                       \
            v.y = buf[c4 * 4 + 1][x];                                       \
            v.z = buf[c4 * 4 + 2][x];                                       \
            v.w = buf[c4 * 4 + 3][x];                                       \
            reinterpret_cast<float4*>(dst + (size_t)x * FC)[c4] = v;        \
        }                                                                   \
    }

#define BUILD_LEVEL(dstbuf, srcbuf, step)                                   \
    {                                                                       \
        _Pragma("unroll")                                                   \
        for (int it = 0; it < 8; ++it) {                                    \
            int idx = tid + it * 256;                                       \
            int c = idx >> 6;                                               \
            int x = idx & 63;                                               \
            int x2 = min(x + (step), 63);                                   \
            dstbuf[c][x] = fmaxf(srcbuf[c][x], srcbuf[c][x2]);              \
        }                                                                   \
    }

    STORE_LEVEL(sA, 0)
    BUILD_LEVEL(sB, sA, 1)
    __syncthreads();
    STORE_LEVEL(sB, 1)
    BUILD_LEVEL(sA, sB, 2)
    __syncthreads();
    STORE_LEVEL(sA, 2)
    BUILD_LEVEL(sB, sA, 4)
    __syncthreads();
    STORE_LEVEL(sB, 3)
#undef STORE_LEVEL
#undef BUILD_LEVEL
}

// ---------------------------------------------------------------------------
// Kernel 2: one block (224 thr = 7 warps) per (roi, ph) stripe: 1792 blocks.
// Warp = bin column pw; lane = channel chunk. Bin row-segment = 2 pyramid
// lookups (sparse-table RMQ). Y-loop FULLY UNROLLED to 10 with predicated
// loads: all <=20 independent LDG.128 issue before any dependent fmax ->
// one latency exposure per warp instead of one per 2 rows.
// ---------------------------------------------------------------------------
__global__ __launch_bounds__(224, 4) void roipool_kernel(const float* __restrict__ rois,
                                                         float* __restrict__ out) {
    __shared__ float s_acc[OW][FC];          // 3.5 KB
    __shared__ int s_q[OW][3];               // k, xs0, xs1 per pw
    __shared__ int s_geo[4];                 // b, hs, he, empty

    int bx = blockIdx.x;
    int r  = bx / OH;
    int ph = bx - r * OH;
    int tid  = threadIdx.x;
    int wid  = tid >> 5;                     // == pw (7 warps)
    int lane = tid & 31;

    if (tid < OW) {
        int x1 = (int)(rois[r * 5 + 1] * SCALE);
        int x2 = (int)(rois[r * 5 + 3] * SCALE);
        int w = x2 - x1;
        int ws = x1 + (tid * w) / OW;
        int we = x1 + ((tid + 1) * w + OW - 1) / OW;
        int wp = we - ws;
        int k  = (wp > 0) ? (31 - __clz(wp)) : 0;   // wp <= 10 -> k <= 3
        s_q[tid][0] = k;
        s_q[tid][1] = ws;
        s_q[tid][2] = (wp > 0) ? (we - (1 << k)) : ws;
    } else if (tid < 8) {                    // tid == 7
        int b  = (int)rois[r * 5 + 0];
        int x1 = (int)(rois[r * 5 + 1] * SCALE);
        int y1 = (int)(rois[r * 5 + 2] * SCALE);
        int x2 = (int)(rois[r * 5 + 3] * SCALE);
        int y2 = (int)(rois[r * 5 + 4] * SCALE);
        int h = y2 - y1;
        int w = x2 - x1;
        s_geo[0] = b;
        s_geo[1] = y1 + (ph * h) / OH;
        s_geo[2] = y1 + ((ph + 1) * h + OH - 1) / OH;
        s_geo[3] = (h <= 0 || w <= 0);
    }
    __syncthreads();

    int b  = s_geo[0];
    int hs = s_geo[1];
    int he = s_geo[2];
    int empty = s_geo[3];

    {
        int k   = s_q[wid][0];
        int xs0 = s_q[wid][1];
        int xs1 = s_q[wid][2];

        const float4 NEG4 = make_float4(-CUDART_INF_F, -CUDART_INF_F,
                                        -CUDART_INF_F, -CUDART_INF_F);
        float4 acc = NEG4;

        const float4* base = reinterpret_cast<const float4*>(g_pyr[k])
                           + ((size_t)b * FH * FW) * C4 + lane;
        const float4* p0 = base + (size_t)xs0 * C4;
        const float4* p1 = base + (size_t)xs1 * C4;

        #pragma unroll
        for (int i = 0; i < MAXROWS; ++i) {
            int y = hs + i;
            bool ok = (y < he);
            size_t ro = (size_t)(y * FW) * C4;
            // predicated loads: no memory traffic when ok==false
            float4 v0 = ok ? p0[ro] : NEG4;
            float4 v1 = ok ? p1[ro] : NEG4;
            acc.x = fmaxf(acc.x, fmaxf(v0.x, v1.x));
            acc.y = fmaxf(acc.y, fmaxf(v0.y, v1.y));
            acc.z = fmaxf(acc.z, fmaxf(v0.z, v1.z));
            acc.w = fmaxf(acc.w, fmaxf(v0.w, v1.w));
        }
        reinterpret_cast<float4*>(s_acc[wid])[lane] = acc;
    }
    __syncthreads();

    // Epilogue: 896 outputs for this (r, ph) slice: out[r][c][ph][pw]
    float* obase = out + (size_t)r * FC * NBIN + ph * OW;
    #pragma unroll
    for (int it = 0; it < 4; ++it) {
        int t = tid + it * 224;
        int c  = t / OW;
        int pw = t - c * OW;
        obase[c * NBIN + pw] = empty ? 0.f : s_acc[pw][c];
    }
}

extern "C" void kernel_launch(void* const* d_in, const int* in_sizes, int n_in,
                              void* d_out, int out_size) {
    const float* feat = (const float*)d_in[0];   // (2,128,64,64) fp32
    const float* rois = (const float*)d_in[1];   // (256,5) fp32
    float* out = (float*)d_out;                  // (256,128,7,7) fp32

    transpose_build<<<NB * FH * 4, 256>>>(feat);
    roipool_kernel<<<NROI * OH, 224>>>(rois, out);
}

// round 12
// speedup vs baseline: 1.1292x; 1.0215x over previous
#include <cuda_runtime.h>
#include <math_constants.h>

#define FH 64
#define FW 64
#define FC 128
#define NB 2
#define NROI 256
#define OH 7
#define OW 7
#define NBIN (OH * OW)          // 49
#define SCALE 0.0625f
#define C4 (FC / 4)             // 32 float4 per pixel
#define LVL (NB * FH * FW * FC) // floats per pyramid level (4 MB)

// x-max pyramid, NHWC per level: level k = max over columns [x, x+2^k), k=0..3
__device__ float g_pyr[4][LVL];

// ---------------------------------------------------------------------------
// Kernel 1: NCHW -> NHWC transpose + x-max pyramid build.
// One block per (b, y, channel-quarter): 512 blocks, 32ch x 64px tiles.
// ---------------------------------------------------------------------------
__global__ __launch_bounds__(256) void transpose_build(const float* __restrict__ feat) {
    __shared__ float sA[32][FW + 1];         // 8.3 KB
    __shared__ float sB[32][FW + 1];         // 8.3 KB
    int blk = blockIdx.x;                    // 0..511
    int choff = (blk & 3) * 32;              // channel quarter
    int row = blk >> 2;                      // b*64 + y
    int b = row >> 6;
    int y = row & 63;
    int tid = threadIdx.x;

    const float4* src4 = reinterpret_cast<const float4*>(
        feat + (((size_t)b * FC + choff) * FH + y) * FW);
    const size_t cstr4 = (size_t)FH * FW / 4;
    #pragma unroll
    for (int it = 0; it < 2; ++it) {
        int idx = tid + it * 256;            // 0..511
        int c  = idx >> 4;
        int x4 = idx & 15;
        float4 v = src4[(size_t)c * cstr4 + x4];
        sA[c][x4 * 4 + 0] = v.x;
        sA[c][x4 * 4 + 1] = v.y;
        sA[c][x4 * 4 + 2] = v.z;
        sA[c][x4 * 4 + 3] = v.w;
    }
    __syncthreads();

    size_t dbase = (size_t)row * FW * FC + choff;

#define STORE_LEVEL(buf, k)                                                 \
    {                                                                       \
        float* dst = g_pyr[k] + dbase;                                      \
        _Pragma("unroll")                                                   \
        for (int it = 0; it < 2; ++it) {                                    \
            int idx = tid + it * 256;                                       \
            int c4 = idx & 7;                                               \
            int x  = idx >> 3;                                              \
            float4 v;                                                       \
            v.x = buf[c4 * 4 + 0][x];                                       \
            v.y = buf[c4 * 4 + 1][x];                                       \
            v.z = buf[c4 * 4 + 2][x];                                       \
            v.w = buf[c4 * 4 + 3][x];                                       \
            reinterpret_cast<float4*>(dst + (size_t)x * FC)[c4] = v;        \
        }                                                                   \
    }

#define BUILD_LEVEL(dstbuf, srcbuf, step)                                   \
    {                                                                       \
        _Pragma("unroll")                                                   \
        for (int it = 0; it < 8; ++it) {                                    \
            int idx = tid + it * 256;                                       \
            int c = idx >> 6;                                               \
            int x = idx & 63;                                               \
            int x2 = min(x + (step), 63);                                   \
            dstbuf[c][x] = fmaxf(srcbuf[c][x], srcbuf[c][x2]);              \
        }                                                                   \
    }

    STORE_LEVEL(sA, 0)
    BUILD_LEVEL(sB, sA, 1)
    __syncthreads();
    STORE_LEVEL(sB, 1)
    BUILD_LEVEL(sA, sB, 2)
    __syncthreads();
    STORE_LEVEL(sA, 2)
    BUILD_LEVEL(sB, sA, 4)
    __syncthreads();
    STORE_LEVEL(sB, 3)
#undef STORE_LEVEL
#undef BUILD_LEVEL
}

// ---------------------------------------------------------------------------
// Kernel 2: one block (224 thr = 7 warps) per (roi, ph) stripe: 1792 blocks.
// Warp = bin column pw; lane = channel chunk. Bin row-segment = 2 pyramid
// lookups (sparse-table RMQ). Rows processed in predicated 4-batches:
// 8 independent LDG.128 in flight per stall, trips 1-3, regs stay moderate.
// Launched with PDL: ROI decode overlaps transpose_build's tail; grid-dep
// sync before first pyramid read.
// ---------------------------------------------------------------------------
__global__ __launch_bounds__(224) void roipool_kernel(const float* __restrict__ rois,
                                                      float* __restrict__ out) {
    __shared__ float s_acc[OW][FC];          // 3.5 KB
    __shared__ int s_q[OW][3];               // k, xs0, xs1 per pw
    __shared__ int s_geo[4];                 // b, hs, he, empty

    int bx = blockIdx.x;
    int r  = bx / OH;
    int ph = bx - r * OH;
    int tid  = threadIdx.x;
    int wid  = tid >> 5;                     // == pw (7 warps)
    int lane = tid & 31;

    if (tid < OW) {
        int x1 = (int)(rois[r * 5 + 1] * SCALE);
        int x2 = (int)(rois[r * 5 + 3] * SCALE);
        int w = x2 - x1;
        int ws = x1 + (tid * w) / OW;
        int we = x1 + ((tid + 1) * w + OW - 1) / OW;
        int wp = we - ws;
        int k  = (wp > 0) ? (31 - __clz(wp)) : 0;   // wp <= 10 -> k <= 3
        s_q[tid][0] = k;
        s_q[tid][1] = ws;
        s_q[tid][2] = (wp > 0) ? (we - (1 << k)) : ws;
    } else if (tid < 8) {                    // tid == 7
        int b  = (int)rois[r * 5 + 0];
        int x1 = (int)(rois[r * 5 + 1] * SCALE);
        int y1 = (int)(rois[r * 5 + 2] * SCALE);
        int x2 = (int)(rois[r * 5 + 3] * SCALE);
        int y2 = (int)(rois[r * 5 + 4] * SCALE);
        int h = y2 - y1;
        int w = x2 - x1;
        s_geo[0] = b;
        s_geo[1] = y1 + (ph * h) / OH;
        s_geo[2] = y1 + ((ph + 1) * h + OH - 1) / OH;
        s_geo[3] = (h <= 0 || w <= 0);
    }
    __syncthreads();

    int b  = s_geo[0];
    int hs = s_geo[1];
    int he = s_geo[2];
    int empty = s_geo[3];

    // PDL: wait for transpose_build's pyramid writes before reading them.
    cudaGridDependencySynchronize();

    {
        int k   = s_q[wid][0];
        int xs0 = s_q[wid][1];
        int xs1 = s_q[wid][2];

        const float4 NEG4 = make_float4(-CUDART_INF_F, -CUDART_INF_F,
                                        -CUDART_INF_F, -CUDART_INF_F);
        float4 acc = NEG4;

        const float4* base = reinterpret_cast<const float4*>(g_pyr[k])
                           + ((size_t)b * FH * FW) * C4 + lane;
        const float4* p0 = base + (size_t)xs0 * C4;
        const float4* p1 = base + (size_t)xs1 * C4;

        for (int y = hs; y < he; y += 4) {   // predicated 4-row batches
            float4 v[8];
            #pragma unroll
            for (int i = 0; i < 4; ++i) {
                bool ok = (y + i) < he;
                size_t ro = (size_t)((y + i) * FW) * C4;
                v[2 * i + 0] = ok ? p0[ro] : NEG4;   // no traffic if !ok
                v[2 * i + 1] = ok ? p1[ro] : NEG4;
            }
            #pragma unroll
            for (int i = 0; i < 8; ++i) {
                acc.x = fmaxf(acc.x, v[i].x);
                acc.y = fmaxf(acc.y, v[i].y);
                acc.z = fmaxf(acc.z, v[i].z);
                acc.w = fmaxf(acc.w, v[i].w);
            }
        }
        reinterpret_cast<float4*>(s_acc[wid])[lane] = acc;
    }
    __syncthreads();

    // Epilogue: 896 outputs for this (r, ph) slice: out[r][c][ph][pw]
    float* obase = out + (size_t)r * FC * NBIN + ph * OW;
    #pragma unroll
    for (int it = 0; it < 4; ++it) {
        int t = tid + it * 224;
        int c  = t / OW;
        int pw = t - c * OW;
        obase[c * NBIN + pw] = empty ? 0.f : s_acc[pw][c];
    }
}

extern "C" void kernel_launch(void* const* d_in, const int* in_sizes, int n_in,
                              void* d_out, int out_size) {
    const float* feat = (const float*)d_in[0];   // (2,128,64,64) fp32
    const float* rois = (const float*)d_in[1];   // (256,5) fp32
    float* out = (float*)d_out;                  // (256,128,7,7) fp32

    transpose_build<<<NB * FH * 4, 256>>>(feat);

    // Pool kernel with programmatic dependent launch: prologue overlaps
    // transpose_build's tail; device-side gridDependencySynchronize orders
    // the pyramid reads.
    cudaLaunchConfig_t cfg = {};
    cfg.gridDim  = dim3(NROI * OH);
    cfg.blockDim = dim3(224);
    cfg.stream   = 0;
    cudaLaunchAttribute attrs[1];
    attrs[0].id = cudaLaunchAttributeProgrammaticStreamSerialization;
    attrs[0].val.programmaticStreamSerializationAllowed = 1;
    cfg.attrs = attrs;
    cfg.numAttrs = 1;
    cudaLaunchKernelEx(&cfg, roipool_kernel, rois, out);
}

// round 15
// speedup vs baseline: 1.2355x; 1.0942x over previous
#include <cuda_runtime.h>
#include <math_constants.h>

#define FH 64
#define FW 64
#define FC 128
#define NB 2
#define NROI 256
#define OH 7
#define OW 7
#define NBIN (OH * OW)          // 49
#define SCALE 0.0625f
#define C4 (FC / 4)             // 32 float4 per pixel
#define LVL (NB * FH * FW * FC) // floats per pyramid level (4 MB)

// x-max pyramid, NHWC per level: level k = max over columns [x, x+2^k), k=0..3
__device__ float g_pyr[4][LVL];

// ---------------------------------------------------------------------------
// Kernel 1: NCHW -> NHWC transpose + x-max pyramid build.
// One block per (b, y, channel-quarter): 512 blocks, 32ch x 64px tiles.
// ---------------------------------------------------------------------------
__global__ __launch_bounds__(256) void transpose_build(const float* __restrict__ feat) {
    __shared__ float sA[32][FW + 1];         // 8.3 KB
    __shared__ float sB[32][FW + 1];         // 8.3 KB
    int blk = blockIdx.x;                    // 0..511
    int choff = (blk & 3) * 32;              // channel quarter
    int row = blk >> 2;                      // b*64 + y
    int b = row >> 6;
    int y = row & 63;
    int tid = threadIdx.x;

    const float4* src4 = reinterpret_cast<const float4*>(
        feat + (((size_t)b * FC + choff) * FH + y) * FW);
    const size_t cstr4 = (size_t)FH * FW / 4;
    #pragma unroll
    for (int it = 0; it < 2; ++it) {
        int idx = tid + it * 256;            // 0..511
        int c  = idx >> 4;
        int x4 = idx & 15;
        float4 v = src4[(size_t)c * cstr4 + x4];
        sA[c][x4 * 4 + 0] = v.x;
        sA[c][x4 * 4 + 1] = v.y;
        sA[c][x4 * 4 + 2] = v.z;
        sA[c][x4 * 4 + 3] = v.w;
    }
    __syncthreads();

    size_t dbase = (size_t)row * FW * FC + choff;

#define STORE_LEVEL(buf, k)                                                 \
    {                                                                       \
        float* dst = g_pyr[k] + dbase;                                      \
        _Pragma("unroll")                                                   \
        for (int it = 0; it < 2; ++it) {                                    \
            int idx = tid + it * 256;                                       \
            int c4 = idx & 7;                                               \
            int x  = idx >> 3;                                              \
            float4 v;                                                       \
            v.x = buf[c4 * 4 + 0][x];                                       \
            v.y = buf[c4 * 4 + 1][x];                                       \
            v.z = buf[c4 * 4 + 2][x];                                       \
            v.w = buf[c4 * 4 + 3][x];                                       \
            reinterpret_cast<float4*>(dst + (size_t)x * FC)[c4] = v;        \
        }                                                                   \
    }

#define BUILD_LEVEL(dstbuf, srcbuf, step)                                   \
    {                                                                       \
        _Pragma("unroll")                                                   \
        for (int it = 0; it < 8; ++it) {                                    \
            int idx = tid + it * 256;                                       \
            int c = idx >> 6;                                               \
            int x = idx & 63;                                               \
            int x2 = min(x + (step), 63);                                   \
            dstbuf[c][x] = fmaxf(srcbuf[c][x], srcbuf[c][x2]);              \
        }                                                                   \
    }

    STORE_LEVEL(sA, 0)
    BUILD_LEVEL(sB, sA, 1)
    __syncthreads();
    STORE_LEVEL(sB, 1)
    BUILD_LEVEL(sA, sB, 2)
    __syncthreads();
    STORE_LEVEL(sA, 2)
    BUILD_LEVEL(sB, sA, 4)
    __syncthreads();
    STORE_LEVEL(sB, 3)
#undef STORE_LEVEL
#undef BUILD_LEVEL
}

// ---------------------------------------------------------------------------
// Kernel 2 (R9 body): one block (224 thr = 7 warps) per (roi, ph) stripe:
// 1792 blocks. Warp = bin column pw; lane = channel chunk. Bin row-segment
// = 2 pyramid lookups (sparse-table RMQ); dynamic y-loop, unroll 2.
// PDL: decode runs during transpose drain; grid-dep sync before pyramid read.
// ---------------------------------------------------------------------------
__global__ __launch_bounds__(224, 8) void roipool_kernel(const float* __restrict__ rois,
                                                         float* __restrict__ out) {
    __shared__ float s_acc[OW][FC];          // 3.5 KB
    __shared__ int s_q[OW][3];               // k, xs0, xs1 per pw
    __shared__ int s_geo[4];                 // b, hs, he, empty

    int bx = blockIdx.x;
    int r  = bx / OH;
    int ph = bx - r * OH;
    int tid  = threadIdx.x;
    int wid  = tid >> 5;                     // == pw (7 warps)
    int lane = tid & 31;

    if (tid < OW) {
        int x1 = (int)(rois[r * 5 + 1] * SCALE);
        int x2 = (int)(rois[r * 5 + 3] * SCALE);
        int w = x2 - x1;
        int ws = x1 + (tid * w) / OW;
        int we = x1 + ((tid + 1) * w + OW - 1) / OW;
        int wp = we - ws;
        int k  = (wp > 0) ? (31 - __clz(wp)) : 0;   // wp <= 10 -> k <= 3
        s_q[tid][0] = k;
        s_q[tid][1] = ws;
        s_q[tid][2] = (wp > 0) ? (we - (1 << k)) : ws;
    } else if (tid < 8) {                    // tid == 7
        int b  = (int)rois[r * 5 + 0];
        int x1 = (int)(rois[r * 5 + 1] * SCALE);
        int y1 = (int)(rois[r * 5 + 2] * SCALE);
        int x2 = (int)(rois[r * 5 + 3] * SCALE);
        int y2 = (int)(rois[r * 5 + 4] * SCALE);
        int h = y2 - y1;
        int w = x2 - x1;
        s_geo[0] = b;
        s_geo[1] = y1 + (ph * h) / OH;
        s_geo[2] = y1 + ((ph + 1) * h + OH - 1) / OH;
        s_geo[3] = (h <= 0 || w <= 0);
    }
    __syncthreads();

    int b  = s_geo[0];
    int hs = s_geo[1];
    int he = s_geo[2];
    int empty = s_geo[3];

    // PDL: transpose_build's pyramid writes must be visible past this point.
    cudaGridDependencySynchronize();

    {
        int k   = s_q[wid][0];
        int xs0 = s_q[wid][1];
        int xs1 = s_q[wid][2];

        float4 acc = make_float4(-CUDART_INF_F, -CUDART_INF_F,
                                 -CUDART_INF_F, -CUDART_INF_F);

        const float4* base = reinterpret_cast<const float4*>(g_pyr[k])
                           + ((size_t)b * FH * FW) * C4 + lane;
        const float4* p0 = base + (size_t)xs0 * C4;
        const float4* p1 = base + (size_t)xs1 * C4;

        #pragma unroll 2
        for (int y = hs; y < he; ++y) {
            size_t ro = (size_t)(y * FW) * C4;
            float4 v0 = p0[ro];              // 2 independent loads per row
            float4 v1 = p1[ro];
            acc.x = fmaxf(acc.x, fmaxf(v0.x, v1.x));
            acc.y = fmaxf(acc.y, fmaxf(v0.y, v1.y));
            acc.z = fmaxf(acc.z, fmaxf(v0.z, v1.z));
            acc.w = fmaxf(acc.w, fmaxf(v0.w, v1.w));
        }
        reinterpret_cast<float4*>(s_acc[wid])[lane] = acc;
    }
    __syncthreads();

    // Epilogue: 896 outputs for this (r, ph) slice: out[r][c][ph][pw].
    // Division hoisted: thread owns (c0 = tid/7, pw = tid%7), c += 32/iter.
    float* obase = out + (size_t)r * FC * NBIN + ph * OW;
    int c0 = tid / OW;
    int pw = tid - c0 * OW;
    #pragma unroll
    for (int it = 0; it < 4; ++it) {
        int c = c0 + it * 32;
        obase[c * NBIN + pw] = empty ? 0.f : s_acc[pw][c];
    }
}

extern "C" void kernel_launch(void* const* d_in, const int* in_sizes, int n_in,
                              void* d_out, int out_size) {
    const float* feat = (const float*)d_in[0];   // (2,128,64,64) fp32
    const float* rois = (const float*)d_in[1];   // (256,5) fp32
    float* out = (float*)d_out;                  // (256,128,7,7) fp32

    transpose_build<<<NB * FH * 4, 256>>>(feat);

    // Pool kernel with programmatic dependent launch (R12-proven config,
    // implicit completion — no explicit trigger).
    cudaLaunchConfig_t cfg = {};
    cfg.gridDim  = dim3(NROI * OH);
    cfg.blockDim = dim3(224);
    cfg.stream   = 0;
    cudaLaunchAttribute attrs[1];
    attrs[0].id = cudaLaunchAttributeProgrammaticStreamSerialization;
    attrs[0].val.programmaticStreamSerializationAllowed = 1;
    cfg.attrs = attrs;
    cfg.numAttrs = 1;
    cudaLaunchKernelEx(&cfg, roipool_kernel, rois, out);
}